// round 9
// baseline (speedup 1.0000x reference)
#include <cuda_runtime.h>
#include <cuda_bf16.h>

// ---------------------------------------------------------------------------
// SS2D: B=4, H=W=56, L=3136, d_model=96, d_inner=192, N=16, K=4 dirs, rank=6
// ---------------------------------------------------------------------------

#define L_LEN   3136
#define D_IN    192
#define N_ST    16
#define M_ROWS  12544        // B*L
#define NCHUNK  64
#define CLEN    49

typedef unsigned long long u64;

// ---------------- packed f32x2 helpers -------------------------------------
__device__ __forceinline__ u64 fma2(u64 a, u64 b, u64 c) {
    u64 d;
    asm("fma.rn.f32x2 %0, %1, %2, %3;" : "=l"(d) : "l"(a), "l"(b), "l"(c));
    return d;
}
__device__ __forceinline__ float2 unpk(u64 v) {
    unsigned lo, hi;
    asm("mov.b64 {%0, %1}, %2;" : "=r"(lo), "=r"(hi) : "l"(v));
    return make_float2(__uint_as_float(lo), __uint_as_float(hi));
}

// ---------------- scratch (static device globals) --------------------------
__device__ __align__(256) float g_xcraw [M_ROWS * D_IN];
__device__ __align__(256) float g_xc    [M_ROWS * D_IN];
__device__ __align__(256) float g_z     [M_ROWS * D_IN];
__device__ __align__(256) float g_proj  [16 * L_LEN * 40];
__device__ __align__(256) float g_cA    [16 * NCHUNK * D_IN * N_ST];
__device__ __align__(256) float g_cH    [16 * NCHUNK * D_IN * N_ST];
__device__ __align__(256) float g_hs    [16 * NCHUNK * D_IN * N_ST];
__device__ __align__(256) float g_yout  [16 * L_LEN * D_IN];
__device__ __align__(256) float g_gated [M_ROWS * D_IN];

// ---------------------------------------------------------------------------
// GEMM: C = A @ W^T, tile 64x64, BK=16, 256 threads, 4x4 micro-tile.
// A-tile stored DUPLICATED ({a,a} pairs) so inner loop = 3 LDS.128 + 8 FFMA2.
// SEL0: A=x [M,96],       W=in_proj [384,96]   -> xcraw | silu->z
// SEL1: A=g_xc [M,192],   W=xpw flat [152,192] -> g_proj (dir-mapped)
// SEL2: A=g_gated [M,192],W=out_w [96,192]     -> out (cols guarded < 96)
// ---------------------------------------------------------------------------
template<int SEL>
__global__ void __launch_bounds__(256)
gemm_tn(const float* __restrict__ Aopt, const float* __restrict__ W,
        float* __restrict__ Copt, int N, int Kd)
{
    __shared__ float As2[16][136];   // duplicated pairs: [kk][2*col+{0,1}]
    __shared__ float Ws [16][68];

    const float* A;
    if      (SEL == 0) A = Aopt;
    else if (SEL == 1) A = g_xc;
    else               A = g_gated;

    int t  = threadIdx.x;
    int bm = blockIdx.x, bn = blockIdx.y;

    int lm  = t >> 2;            // 0..63
    int kq  = (t & 3) * 4;       // 0,4,8,12
    int m_g = bm * 64 + lm;
    int n_g = bn * 64 + lm;
    bool wok = (n_g < N);

    int ty = t >> 4, tx = t & 15;   // rows ty*4+i, cols tx*4+j

    u64 acc[4][2];
    #pragma unroll
    for (int i = 0; i < 4; i++) { acc[i][0] = 0ull; acc[i][1] = 0ull; }

    for (int k0 = 0; k0 < Kd; k0 += 16) {
        float4 av = *(const float4*)&A[m_g * Kd + k0 + kq];
        float4 wv = make_float4(0.f, 0.f, 0.f, 0.f);
        if (wok) wv = *(const float4*)&W[n_g * Kd + k0 + kq];
        __syncthreads();
        As2[kq + 0][2 * lm] = av.x; As2[kq + 0][2 * lm + 1] = av.x;
        As2[kq + 1][2 * lm] = av.y; As2[kq + 1][2 * lm + 1] = av.y;
        As2[kq + 2][2 * lm] = av.z; As2[kq + 2][2 * lm + 1] = av.z;
        As2[kq + 3][2 * lm] = av.w; As2[kq + 3][2 * lm + 1] = av.w;
        Ws[kq + 0][lm] = wv.x; Ws[kq + 1][lm] = wv.y;
        Ws[kq + 2][lm] = wv.z; Ws[kq + 3][lm] = wv.w;
        __syncthreads();
        #pragma unroll
        for (int kk = 0; kk < 16; kk++) {
            ulonglong2 aa0 = *(const ulonglong2*)&As2[kk][8 * ty];
            ulonglong2 aa1 = *(const ulonglong2*)&As2[kk][8 * ty + 4];
            ulonglong2 bb  = *(const ulonglong2*)&Ws[kk][tx * 4];
            acc[0][0] = fma2(aa0.x, bb.x, acc[0][0]);
            acc[0][1] = fma2(aa0.x, bb.y, acc[0][1]);
            acc[1][0] = fma2(aa0.y, bb.x, acc[1][0]);
            acc[1][1] = fma2(aa0.y, bb.y, acc[1][1]);
            acc[2][0] = fma2(aa1.x, bb.x, acc[2][0]);
            acc[2][1] = fma2(aa1.x, bb.y, acc[2][1]);
            acc[3][0] = fma2(aa1.y, bb.x, acc[3][0]);
            acc[3][1] = fma2(aa1.y, bb.y, acc[3][1]);
        }
    }

    int cbase = bn * 64 + tx * 4;
    #pragma unroll
    for (int i = 0; i < 4; i++) {
        int gr = bm * 64 + ty * 4 + i;
        float2 v0 = unpk(acc[i][0]);
        float2 v1 = unpk(acc[i][1]);
        float v[4] = {v0.x, v0.y, v1.x, v1.y};

        if (SEL == 0) {
            if (cbase < D_IN) {
                *(float4*)&g_xcraw[gr * D_IN + cbase] =
                    make_float4(v[0], v[1], v[2], v[3]);
            } else {
                float4 s;
                s.x = v[0] / (1.f + __expf(-v[0]));
                s.y = v[1] / (1.f + __expf(-v[1]));
                s.z = v[2] / (1.f + __expf(-v[2]));
                s.w = v[3] / (1.f + __expf(-v[3]));
                *(float4*)&g_z[gr * D_IN + cbase - D_IN] = s;
            }
        } else if (SEL == 2) {
            if (cbase < 96)      // guard: N=96, tile spans 128 cols
                *(float4*)&Copt[gr * 96 + cbase] =
                    make_float4(v[0], v[1], v[2], v[3]);
        } else {
            int b   = gr / L_LEN;
            int pos = gr - b * L_LEN;
            int h = pos / 56, w = pos - h * 56;
            int tp = w * 56 + h;
            #pragma unroll
            for (int j = 0; j < 4; j++) {
                int gc = cbase + j;
                if (gc < 152) {
                    int k = gc / 38;
                    int c = gc - k * 38;
                    int cc = (c < 6) ? c : c + 2;
                    int l = (k == 0) ? pos : (k == 1) ? tp
                          : (k == 2) ? (L_LEN - 1 - pos) : (L_LEN - 1 - tp);
                    g_proj[((b * 4 + k) * L_LEN + l) * 40 + cc] = v[j];
                }
            }
        }
    }
}

// ---------------------------------------------------------------------------
__global__ void __launch_bounds__(256)
conv_dw_kernel(const float* __restrict__ cw, const float* __restrict__ cb)
{
    int idx = blockIdx.x * 256 + threadIdx.x;      // < 12544*192
    int d = idx % D_IN;
    int m = idx / D_IN;
    int pos = m % L_LEN;
    int b   = m / L_LEN;
    int h = pos / 56, w = pos % 56;
    float acc = cb[d];
    #pragma unroll
    for (int kh = 0; kh < 3; kh++) {
        int hh = h + kh - 1;
        if (hh < 0 || hh >= 56) continue;
        #pragma unroll
        for (int kw = 0; kw < 3; kw++) {
            int ww = w + kw - 1;
            if (ww < 0 || ww >= 56) continue;
            acc = fmaf(g_xcraw[(b * L_LEN + hh * 56 + ww) * D_IN + d],
                       cw[d * 9 + kh * 3 + kw], acc);
        }
    }
    g_xc[idx] = acc / (1.f + __expf(-acc));        // SiLU
}

// ---------------------------------------------------------------------------
// direction geometry: initial pos + stride for incremental update
__device__ __forceinline__ void dir_init(int k, int l0, int& pos, int& dpos) {
    if (k == 0)      { pos = l0;                           dpos = 1;  }
    else if (k == 2) { pos = L_LEN - 1 - l0;               dpos = -1; }
    else if (k == 1) { pos = (l0 % 56) * 56 + l0 / 56;     dpos = 56; }
    else { int l2 = L_LEN - 1 - l0;
           pos = (l2 % 56) * 56 + l2 / 56;                 dpos = -56; }
}
__device__ __forceinline__ int pos_step(int pos, int dpos) {
    pos += dpos;
    if (pos >= L_LEN) pos -= (L_LEN - 1);
    if (pos < 0)      pos += (L_LEN - 1);
    return pos;
}

// 8 powers of e1 (tree): E[j] = e1^(j+1), j=0..7
__device__ __forceinline__ void pow_tree8(float e1, float* E) {
    float e2 = e1 * e1;
    float e4 = e2 * e2;
    E[0] = e1;      E[1] = e2;      E[2] = e2 * e1; E[3] = e4;
    E[4] = e4 * e1; E[5] = e4 * e2; E[6] = e4 * E[2]; E[7] = e4 * e4;
}

// inline delta: softplus(bias + dtw . proj[0..5])
__device__ __forceinline__ float delta_of(const float4 p0, const float2 p1,
                                          float2 w0, float2 w1, float2 w2,
                                          float bias) {
    float s = bias;
    s = fmaf(w0.x, p0.x, s);
    s = fmaf(w0.y, p0.y, s);
    s = fmaf(w1.x, p0.z, s);
    s = fmaf(w1.y, p0.w, s);
    s = fmaf(w2.x, p1.x, s);
    s = fmaf(w2.y, p1.y, s);
    return fmaxf(s, 0.f) + __logf(1.f + __expf(-fabsf(s)));
}

// ---------------------------------------------------------------------------
// Phase 1: per-chunk local scan, SPLIT: 2 threads per d channel, 8 states
// each (half = tid&1 owns n in [half*8, half*8+8)). 384 threads/block.
// ---------------------------------------------------------------------------
__global__ void __launch_bounds__(384)
scan_phase1(const float* __restrict__ A_logs,
            const float* __restrict__ dtw, const float* __restrict__ dtb)
{
    int bid = blockIdx.x;
    int c  = bid & (NCHUNK - 1);
    int bk = bid >> 6;
    int k = bk & 3, b = bk >> 2;
    int tid = threadIdx.x;
    int d    = tid >> 1;
    int half = tid & 1;

    const float* al = &A_logs[(k * D_IN + d) * N_ST];
    float Ar0 = -__expf(al[0]);
    bool pw = true;          // identical for both threads of a pair
    #pragma unroll
    for (int n = 1; n < N_ST; n++) {
        float a = -__expf(al[n]);
        pw = pw && (fabsf(a - (n + 1) * Ar0) <= 1e-4f * (n + 1) * fabsf(Ar0));
    }

    const float* wr = &dtw[(k * D_IN + d) * 6];
    float2 w0 = *(const float2*)wr;
    float2 w1 = *(const float2*)(wr + 2);
    float2 w2 = *(const float2*)(wr + 4);
    float bias = dtb[k * D_IN + d];

    int l0 = c * CLEN;
    int pos, dpos;
    dir_init(k, l0, pos, dpos);

    const float* uptr = &g_xc[b * L_LEN * D_IN + d];
    const float* pp   = &g_proj[(bk * L_LEN + l0) * 40];

    float h[8];
    #pragma unroll
    for (int j = 0; j < 8; j++) h[j] = 0.f;
    float S = 0.f;
    int ob = (bk * NCHUNK + c) * (D_IN * N_ST) + d * N_ST + half * 8;

    if (pw) {
        for (int t = 0; t < CLEN; t++) {
            const float4* prow = (const float4*)(pp + t * 40);
            float4 r0 = prow[0];
            float2 r1 = *(const float2*)(pp + t * 40 + 4);
            float4 qa = prow[2 + 2 * half], qb = prow[3 + 2 * half];
            float u = uptr[pos * D_IN];
            float dt = delta_of(r0, r1, w0, w1, w2, bias);
            S += dt;
            float dtu = dt * u;
            float El[8];
            pow_tree8(__expf(dt * Ar0), El);
            float base = half ? El[7] : 1.f;
            float Bv[8] = {qa.x, qa.y, qa.z, qa.w, qb.x, qb.y, qb.z, qb.w};
            #pragma unroll
            for (int j = 0; j < 8; j++)
                h[j] = fmaf(El[j] * base, h[j], Bv[j] * dtu);
            pos = pos_step(pos, dpos);
        }
        float CA[8];
        pow_tree8(__expf(Ar0 * S), CA);
        float cbase = half ? CA[7] : 1.f;
        *(float4*)&g_cH[ob]     = make_float4(h[0], h[1], h[2], h[3]);
        *(float4*)&g_cH[ob + 4] = make_float4(h[4], h[5], h[6], h[7]);
        *(float4*)&g_cA[ob]     = make_float4(CA[0]*cbase, CA[1]*cbase,
                                              CA[2]*cbase, CA[3]*cbase);
        *(float4*)&g_cA[ob + 4] = make_float4(CA[4]*cbase, CA[5]*cbase,
                                              CA[6]*cbase, CA[7]*cbase);
    } else {
        float arn[8];
        #pragma unroll
        for (int j = 0; j < 8; j++) arn[j] = -__expf(al[half * 8 + j]);
        for (int t = 0; t < CLEN; t++) {
            const float4* prow = (const float4*)(pp + t * 40);
            float4 r0 = prow[0];
            float2 r1 = *(const float2*)(pp + t * 40 + 4);
            float4 qa = prow[2 + 2 * half], qb = prow[3 + 2 * half];
            float u = uptr[pos * D_IN];
            float dt = delta_of(r0, r1, w0, w1, w2, bias);
            S += dt;
            float dtu = dt * u;
            float Bv[8] = {qa.x, qa.y, qa.z, qa.w, qb.x, qb.y, qb.z, qb.w};
            #pragma unroll
            for (int j = 0; j < 8; j++)
                h[j] = fmaf(__expf(dt * arn[j]), h[j], Bv[j] * dtu);
            pos = pos_step(pos, dpos);
        }
        *(float4*)&g_cH[ob]     = make_float4(h[0], h[1], h[2], h[3]);
        *(float4*)&g_cH[ob + 4] = make_float4(h[4], h[5], h[6], h[7]);
        *(float4*)&g_cA[ob]     = make_float4(
            __expf(arn[0]*S), __expf(arn[1]*S),
            __expf(arn[2]*S), __expf(arn[3]*S));
        *(float4*)&g_cA[ob + 4] = make_float4(
            __expf(arn[4]*S), __expf(arn[5]*S),
            __expf(arn[6]*S), __expf(arn[7]*S));
    }
}

// Phase 2: scan over chunks per (b,k,d,n) channel; store entry state/chunk.
__global__ void __launch_bounds__(256) scan_phase2()
{
    int tid = blockIdx.x * 256 + threadIdx.x;      // < 16*3072
    int bk = tid / (D_IN * N_ST);
    int r  = tid % (D_IN * N_ST);
    float h = 0.f;
    #pragma unroll 4
    for (int c = 0; c < NCHUNK; c++) {
        int idx = (bk * NCHUNK + c) * (D_IN * N_ST) + r;
        g_hs[idx] = h;
        h = fmaf(g_cA[idx], h, g_cH[idx]);
    }
}

// ---------------------------------------------------------------------------
// Phase 3: SPLIT like phase1; re-run chunk with true entry state; y via
// pair shuffle-reduction; emit y + Ds*u.
// ---------------------------------------------------------------------------
__global__ void __launch_bounds__(384)
scan_phase3(const float* __restrict__ A_logs, const float* __restrict__ Ds,
            const float* __restrict__ dtw, const float* __restrict__ dtb)
{
    int bid = blockIdx.x;
    int c  = bid & (NCHUNK - 1);
    int bk = bid >> 6;
    int k = bk & 3, b = bk >> 2;
    int tid = threadIdx.x;
    int d    = tid >> 1;
    int half = tid & 1;

    const float* al = &A_logs[(k * D_IN + d) * N_ST];
    float Ar0 = -__expf(al[0]);
    bool pw = true;
    #pragma unroll
    for (int n = 1; n < N_ST; n++) {
        float a = -__expf(al[n]);
        pw = pw && (fabsf(a - (n + 1) * Ar0) <= 1e-4f * (n + 1) * fabsf(Ar0));
    }

    const float* wr = &dtw[(k * D_IN + d) * 6];
    float2 w0 = *(const float2*)wr;
    float2 w1 = *(const float2*)(wr + 2);
    float2 w2 = *(const float2*)(wr + 4);
    float bias = dtb[k * D_IN + d];

    float h[8];
    int hb = (bk * NCHUNK + c) * (D_IN * N_ST) + d * N_ST + half * 8;
    {
        float4 v0 = *(const float4*)&g_hs[hb];
        float4 v1 = *(const float4*)&g_hs[hb + 4];
        h[0]=v0.x; h[1]=v0.y; h[2]=v0.z; h[3]=v0.w;
        h[4]=v1.x; h[5]=v1.y; h[6]=v1.z; h[7]=v1.w;
    }

    int l0 = c * CLEN;
    int pos, dpos;
    dir_init(k, l0, pos, dpos);

    const float* uptr = &g_xc[b * L_LEN * D_IN + d];
    const float* pp   = &g_proj[(bk * L_LEN + l0) * 40];
    float* yptr = &g_yout[bk * L_LEN * D_IN + d];
    float Dv = Ds[k * D_IN + d];

    if (pw) {
        for (int t = 0; t < CLEN; t++) {
            const float4* prow = (const float4*)(pp + t * 40);
            float4 r0v = prow[0];
            float2 r1v = *(const float2*)(pp + t * 40 + 4);
            float4 qa = prow[2 + 2 * half], qb = prow[3 + 2 * half];
            float4 ca = prow[6 + 2 * half], cbv = prow[7 + 2 * half];
            float u = uptr[pos * D_IN];
            float dt = delta_of(r0v, r1v, w0, w1, w2, bias);
            float dtu = dt * u;
            float El[8];
            pow_tree8(__expf(dt * Ar0), El);
            float base = half ? El[7] : 1.f;
            float Bv[8] = {qa.x, qa.y, qa.z, qa.w, qb.x, qb.y, qb.z, qb.w};
            float Cv[8] = {ca.x, ca.y, ca.z, ca.w, cbv.x, cbv.y, cbv.z, cbv.w};
            float y0 = 0.f, y1 = 0.f;
            #pragma unroll
            for (int j = 0; j < 8; j += 2) {
                h[j]   = fmaf(El[j]   * base, h[j],   Bv[j]   * dtu);
                y0 = fmaf(h[j],   Cv[j],   y0);
                h[j+1] = fmaf(El[j+1] * base, h[j+1], Bv[j+1] * dtu);
                y1 = fmaf(h[j+1], Cv[j+1], y1);
            }
            float yh = y0 + y1;
            float yo = __shfl_xor_sync(0xffffffffu, yh, 1);
            if (half == 0)
                yptr[pos * D_IN] = yh + yo + Dv * u;
            pos = pos_step(pos, dpos);
        }
    } else {
        float arn[8];
        #pragma unroll
        for (int j = 0; j < 8; j++) arn[j] = -__expf(al[half * 8 + j]);
        for (int t = 0; t < CLEN; t++) {
            const float4* prow = (const float4*)(pp + t * 40);
            float4 r0v = prow[0];
            float2 r1v = *(const float2*)(pp + t * 40 + 4);
            float4 qa = prow[2 + 2 * half], qb = prow[3 + 2 * half];
            float4 ca = prow[6 + 2 * half], cbv = prow[7 + 2 * half];
            float u = uptr[pos * D_IN];
            float dt = delta_of(r0v, r1v, w0, w1, w2, bias);
            float dtu = dt * u;
            float Bv[8] = {qa.x, qa.y, qa.z, qa.w, qb.x, qb.y, qb.z, qb.w};
            float Cv[8] = {ca.x, ca.y, ca.z, ca.w, cbv.x, cbv.y, cbv.z, cbv.w};
            float y0 = 0.f, y1 = 0.f;
            #pragma unroll
            for (int j = 0; j < 8; j += 2) {
                h[j]   = fmaf(__expf(dt * arn[j]),   h[j],   Bv[j]   * dtu);
                y0 = fmaf(h[j],   Cv[j],   y0);
                h[j+1] = fmaf(__expf(dt * arn[j+1]), h[j+1], Bv[j+1] * dtu);
                y1 = fmaf(h[j+1], Cv[j+1], y1);
            }
            float yh = y0 + y1;
            float yo = __shfl_xor_sync(0xffffffffu, yh, 1);
            if (half == 0)
                yptr[pos * D_IN] = yh + yo + Dv * u;
            pos = pos_step(pos, dpos);
        }
    }
}

// ---------------------------------------------------------------------------
// Merge 4 directions + LayerNorm(192) + gate with z — one warp per position.
// ---------------------------------------------------------------------------
__global__ void __launch_bounds__(256)
merge_ln_kernel(const float* __restrict__ gamma, const float* __restrict__ beta)
{
    int warp = threadIdx.x >> 5, ln = threadIdx.x & 31;
    int m = blockIdx.x * 8 + warp;       // < 12544 (12544 = 1568*8)
    int b = m / L_LEN;
    int pos = m - b * L_LEN;

    float2 acc[3];
    #pragma unroll
    for (int seg = 0; seg < 3; seg++) {
        int dd = seg * 64 + ln * 2;
        float2 a = make_float2(0.f, 0.f);
        #pragma unroll
        for (int k = 0; k < 4; k++) {
            float2 v = *(const float2*)
                &g_yout[((b * 4 + k) * L_LEN + pos) * D_IN + dd];
            a.x += v.x; a.y += v.y;
        }
        acc[seg] = a;
    }

    float s = 0.f, s2 = 0.f;
    #pragma unroll
    for (int seg = 0; seg < 3; seg++) {
        s  += acc[seg].x + acc[seg].y;
        s2 += acc[seg].x * acc[seg].x + acc[seg].y * acc[seg].y;
    }
    #pragma unroll
    for (int o = 16; o > 0; o >>= 1) {
        s  += __shfl_xor_sync(0xffffffffu, s,  o);
        s2 += __shfl_xor_sync(0xffffffffu, s2, o);
    }
    float mu  = s * (1.f / 192.f);
    float var = s2 * (1.f / 192.f) - mu * mu;
    float rs  = rsqrtf(var + 1e-5f);

    #pragma unroll
    for (int seg = 0; seg < 3; seg++) {
        int dd = seg * 64 + ln * 2;
        float2 gm = *(const float2*)&gamma[dd];
        float2 bt = *(const float2*)&beta[dd];
        float2 zz = *(const float2*)&g_z[m * D_IN + dd];
        float2 o;
        o.x = fmaf((acc[seg].x - mu) * rs, gm.x, bt.x) * zz.x;
        o.y = fmaf((acc[seg].y - mu) * rs, gm.y, bt.y) * zz.y;
        *(float2*)&g_gated[m * D_IN + dd] = o;
    }
}

// ---------------------------------------------------------------------------
extern "C" void kernel_launch(void* const* d_in, const int* in_sizes, int n_in,
                              void* d_out, int out_size)
{
    const float* x      = (const float*)d_in[0];
    const float* in_w   = (const float*)d_in[1];
    const float* conv_w = (const float*)d_in[2];
    const float* conv_b = (const float*)d_in[3];
    const float* xpw    = (const float*)d_in[4];
    const float* dtw    = (const float*)d_in[5];
    const float* dtb    = (const float*)d_in[6];
    const float* A_logs = (const float*)d_in[7];
    const float* Ds     = (const float*)d_in[8];
    const float* gamma  = (const float*)d_in[9];
    const float* beta   = (const float*)d_in[10];
    const float* out_w  = (const float*)d_in[11];
    float* out = (float*)d_out;

    gemm_tn<0><<<dim3(M_ROWS / 64, 6, 1), 256>>>(x, in_w, nullptr, 384, 96);
    conv_dw_kernel<<<(M_ROWS * D_IN) / 256, 256>>>(conv_w, conv_b);
    gemm_tn<1><<<dim3(M_ROWS / 64, 3, 1), 256>>>(nullptr, xpw, nullptr, 152, 192);
    scan_phase1<<<16 * NCHUNK, 384>>>(A_logs, dtw, dtb);
    scan_phase2<<<(16 * D_IN * N_ST) / 256, 256>>>();
    scan_phase3<<<16 * NCHUNK, 384>>>(A_logs, Ds, dtw, dtb);
    merge_ln_kernel<<<M_ROWS / 8, 256>>>(gamma, beta);
    gemm_tn<2><<<dim3(M_ROWS / 64, 2, 1), 256>>>(nullptr, out_w, out, 96, 192);
}

// round 12
// speedup vs baseline: 1.7837x; 1.7837x over previous
#include <cuda_runtime.h>
#include <cuda_bf16.h>

// ---------------------------------------------------------------------------
// SS2D: B=4, H=W=56, L=3136, d_model=96, d_inner=192, N=16, K=4 dirs, rank=6
// ---------------------------------------------------------------------------

#define L_LEN   3136
#define D_IN    192
#define N_ST    16
#define M_ROWS  12544        // B*L
#define NCHUNK  64
#define CLEN    49

typedef unsigned long long u64;

// ---------------- packed f32x2 helpers -------------------------------------
__device__ __forceinline__ u64 pack2(float lo, float hi) {
    u64 d;
    asm("mov.b64 %0, {%1, %2};" : "=l"(d)
        : "r"(__float_as_uint(lo)), "r"(__float_as_uint(hi)));
    return d;
}
__device__ __forceinline__ u64 fma2(u64 a, u64 b, u64 c) {
    u64 d;
    asm("fma.rn.f32x2 %0, %1, %2, %3;" : "=l"(d) : "l"(a), "l"(b), "l"(c));
    return d;
}
__device__ __forceinline__ u64 mul2(u64 a, u64 b) {
    u64 d;
    asm("mul.rn.f32x2 %0, %1, %2;" : "=l"(d) : "l"(a), "l"(b));
    return d;
}
__device__ __forceinline__ float2 unpk(u64 v) {
    unsigned lo, hi;
    asm("mov.b64 {%0, %1}, %2;" : "=r"(lo), "=r"(hi) : "l"(v));
    return make_float2(__uint_as_float(lo), __uint_as_float(hi));
}

// ---------------- scratch (static device globals) --------------------------
__device__ __align__(256) float g_xcraw [M_ROWS * D_IN];
__device__ __align__(256) float g_xc    [M_ROWS * D_IN];
__device__ __align__(256) float g_z     [M_ROWS * D_IN];
__device__ __align__(256) float g_proj  [16 * L_LEN * 40];
__device__ __align__(256) float g_cA    [16 * NCHUNK * D_IN * N_ST];
__device__ __align__(256) float g_cH    [16 * NCHUNK * D_IN * N_ST];
__device__ __align__(256) float g_hs    [16 * NCHUNK * D_IN * N_ST];
__device__ __align__(256) float g_yout  [16 * L_LEN * D_IN];
__device__ __align__(256) float g_gated [M_ROWS * D_IN];

// ---------------------------------------------------------------------------
// GEMM: C = A @ W^T, tile 64x64, BK=16, 256 threads, 4x4 micro-tile.
// A-tile stored DUPLICATED ({a,a} pairs) so inner loop = 3 LDS.128 + 8 FFMA2.
// SEL0: A=x [M,96],       W=in_proj [384,96]   -> xcraw | silu->z
// SEL1: A=g_xc [M,192],   W=xpw flat [152,192] -> g_proj (dir-mapped)
// SEL2: A=g_gated [M,192],W=out_w [96,192]     -> out (cols guarded < 96)
// ---------------------------------------------------------------------------
template<int SEL>
__global__ void __launch_bounds__(256)
gemm_tn(const float* __restrict__ Aopt, const float* __restrict__ W,
        float* __restrict__ Copt, int N, int Kd)
{
    __shared__ float As2[16][136];   // duplicated pairs: [kk][2*col+{0,1}]
    __shared__ float Ws [16][68];

    const float* A;
    if      (SEL == 0) A = Aopt;
    else if (SEL == 1) A = g_xc;
    else               A = g_gated;

    int t  = threadIdx.x;
    int bm = blockIdx.x, bn = blockIdx.y;

    int lm  = t >> 2;            // 0..63
    int kq  = (t & 3) * 4;       // 0,4,8,12
    int m_g = bm * 64 + lm;
    int n_g = bn * 64 + lm;
    bool wok = (n_g < N);

    int ty = t >> 4, tx = t & 15;   // rows ty*4+i, cols tx*4+j

    u64 acc[4][2];
    #pragma unroll
    for (int i = 0; i < 4; i++) { acc[i][0] = 0ull; acc[i][1] = 0ull; }

    for (int k0 = 0; k0 < Kd; k0 += 16) {
        float4 av = *(const float4*)&A[m_g * Kd + k0 + kq];
        float4 wv = make_float4(0.f, 0.f, 0.f, 0.f);
        if (wok) wv = *(const float4*)&W[n_g * Kd + k0 + kq];
        __syncthreads();
        As2[kq + 0][2 * lm] = av.x; As2[kq + 0][2 * lm + 1] = av.x;
        As2[kq + 1][2 * lm] = av.y; As2[kq + 1][2 * lm + 1] = av.y;
        As2[kq + 2][2 * lm] = av.z; As2[kq + 2][2 * lm + 1] = av.z;
        As2[kq + 3][2 * lm] = av.w; As2[kq + 3][2 * lm + 1] = av.w;
        Ws[kq + 0][lm] = wv.x; Ws[kq + 1][lm] = wv.y;
        Ws[kq + 2][lm] = wv.z; Ws[kq + 3][lm] = wv.w;
        __syncthreads();
        #pragma unroll
        for (int kk = 0; kk < 16; kk++) {
            ulonglong2 aa0 = *(const ulonglong2*)&As2[kk][8 * ty];
            ulonglong2 aa1 = *(const ulonglong2*)&As2[kk][8 * ty + 4];
            ulonglong2 bb  = *(const ulonglong2*)&Ws[kk][tx * 4];
            acc[0][0] = fma2(aa0.x, bb.x, acc[0][0]);
            acc[0][1] = fma2(aa0.x, bb.y, acc[0][1]);
            acc[1][0] = fma2(aa0.y, bb.x, acc[1][0]);
            acc[1][1] = fma2(aa0.y, bb.y, acc[1][1]);
            acc[2][0] = fma2(aa1.x, bb.x, acc[2][0]);
            acc[2][1] = fma2(aa1.x, bb.y, acc[2][1]);
            acc[3][0] = fma2(aa1.y, bb.x, acc[3][0]);
            acc[3][1] = fma2(aa1.y, bb.y, acc[3][1]);
        }
    }

    int cbase = bn * 64 + tx * 4;
    #pragma unroll
    for (int i = 0; i < 4; i++) {
        int gr = bm * 64 + ty * 4 + i;
        float2 v0 = unpk(acc[i][0]);
        float2 v1 = unpk(acc[i][1]);
        float v[4] = {v0.x, v0.y, v1.x, v1.y};

        if (SEL == 0) {
            if (cbase < D_IN) {
                *(float4*)&g_xcraw[gr * D_IN + cbase] =
                    make_float4(v[0], v[1], v[2], v[3]);
            } else {
                float4 s;
                s.x = v[0] / (1.f + __expf(-v[0]));
                s.y = v[1] / (1.f + __expf(-v[1]));
                s.z = v[2] / (1.f + __expf(-v[2]));
                s.w = v[3] / (1.f + __expf(-v[3]));
                *(float4*)&g_z[gr * D_IN + cbase - D_IN] = s;
            }
        } else if (SEL == 2) {
            if (cbase < 96)      // guard: N=96, tile spans 128 cols
                *(float4*)&Copt[gr * 96 + cbase] =
                    make_float4(v[0], v[1], v[2], v[3]);
        } else {
            int b   = gr / L_LEN;
            int pos = gr - b * L_LEN;
            int h = pos / 56, w = pos - h * 56;
            int tp = w * 56 + h;
            #pragma unroll
            for (int j = 0; j < 4; j++) {
                int gc = cbase + j;
                if (gc < 152) {
                    int k = gc / 38;
                    int c = gc - k * 38;
                    int cc = (c < 6) ? c : c + 2;
                    int l = (k == 0) ? pos : (k == 1) ? tp
                          : (k == 2) ? (L_LEN - 1 - pos) : (L_LEN - 1 - tp);
                    g_proj[((b * 4 + k) * L_LEN + l) * 40 + cc] = v[j];
                }
            }
        }
    }
}

// ---------------------------------------------------------------------------
__global__ void __launch_bounds__(256)
conv_dw_kernel(const float* __restrict__ cw, const float* __restrict__ cb)
{
    int idx = blockIdx.x * 256 + threadIdx.x;      // < 12544*192
    int d = idx % D_IN;
    int m = idx / D_IN;
    int pos = m % L_LEN;
    int b   = m / L_LEN;
    int h = pos / 56, w = pos % 56;
    float acc = cb[d];
    #pragma unroll
    for (int kh = 0; kh < 3; kh++) {
        int hh = h + kh - 1;
        if (hh < 0 || hh >= 56) continue;
        #pragma unroll
        for (int kw = 0; kw < 3; kw++) {
            int ww = w + kw - 1;
            if (ww < 0 || ww >= 56) continue;
            acc = fmaf(g_xcraw[(b * L_LEN + hh * 56 + ww) * D_IN + d],
                       cw[d * 9 + kh * 3 + kw], acc);
        }
    }
    g_xc[idx] = acc / (1.f + __expf(-acc));        // SiLU
}

// ---------------------------------------------------------------------------
// direction geometry: initial pos + stride for incremental update
__device__ __forceinline__ void dir_init(int k, int l0, int& pos, int& dpos) {
    if (k == 0)      { pos = l0;                           dpos = 1;  }
    else if (k == 2) { pos = L_LEN - 1 - l0;               dpos = -1; }
    else if (k == 1) { pos = (l0 % 56) * 56 + l0 / 56;     dpos = 56; }
    else { int l2 = L_LEN - 1 - l0;
           pos = (l2 % 56) * 56 + l2 / 56;                 dpos = -56; }
}
__device__ __forceinline__ int pos_step(int pos, int dpos) {
    pos += dpos;
    if (pos >= L_LEN) pos -= (L_LEN - 1);
    if (pos < 0)      pos += (L_LEN - 1);
    return pos;
}

// 16 powers of e1 (depth-4 mul tree): E[n] = e1^(n+1)  (epilogue only)
__device__ __forceinline__ void pow_tree16(float e1, float* E) {
    float e2 = e1 * e1;
    float e3 = e2 * e1;
    float e4 = e2 * e2;
    float e8 = e4 * e4;
    E[0] = e1;       E[1] = e2;       E[2] = e3;       E[3] = e4;
    E[4] = e4 * e1;  E[5] = e4 * e2;  E[6] = e4 * e3;  E[7] = e8;
    E[8] = e8 * e1;  E[9] = e8 * e2;  E[10] = e8 * e3; E[11] = e8 * e4;
    E[12] = e8 * E[4]; E[13] = e8 * E[5]; E[14] = e8 * E[6]; E[15] = e8 * e8;
}

// packed powers: p[j] = {e^(2j+1), e^(2j+2)}, j=0..7 (7 mul2 + 4 packs)
__device__ __forceinline__ void pow_tree_pk(float e1, u64* p) {
    float e2 = e1 * e1;
    float e4 = e2 * e2;
    float e8 = e4 * e4;
    p[0] = pack2(e1, e2);
    u64 rr2 = pack2(e2, e2);
    p[1] = mul2(p[0], rr2);
    u64 rr4 = pack2(e4, e4);
    p[2] = mul2(p[0], rr4);
    p[3] = mul2(p[1], rr4);
    u64 rr8 = pack2(e8, e8);
    p[4] = mul2(p[0], rr8);
    p[5] = mul2(p[1], rr8);
    p[6] = mul2(p[2], rr8);
    p[7] = mul2(p[3], rr8);
}

// inline delta: softplus(bias + dtw . proj[0..5])
__device__ __forceinline__ float delta_of(const float4 p0, const float2 p1,
                                          float2 w0, float2 w1, float2 w2,
                                          float bias) {
    float s = bias;
    s = fmaf(w0.x, p0.x, s);
    s = fmaf(w0.y, p0.y, s);
    s = fmaf(w1.x, p0.z, s);
    s = fmaf(w1.y, p0.w, s);
    s = fmaf(w2.x, p1.x, s);
    s = fmaf(w2.y, p1.y, s);
    return fmaxf(s, 0.f) + __logf(1.f + __expf(-fabsf(s)));
}

// ---------------------------------------------------------------------------
// Phase 1: per-chunk local scan (h from 0), dt inline, packed f32x2 h-update.
// Emit local h_end and chunk decay exp(A_n * sum(dt)).
// ---------------------------------------------------------------------------
__global__ void __launch_bounds__(192)
scan_phase1(const float* __restrict__ A_logs,
            const float* __restrict__ dtw, const float* __restrict__ dtb)
{
    int bid = blockIdx.x;
    int c  = bid & (NCHUNK - 1);
    int bk = bid >> 6;
    int k = bk & 3, b = bk >> 2;
    int d = threadIdx.x;

    const float* al = &A_logs[(k * D_IN + d) * N_ST];
    float Ar0 = -__expf(al[0]);
    bool pw = true;
    #pragma unroll
    for (int n = 1; n < N_ST; n++) {
        float a = -__expf(al[n]);
        pw = pw && (fabsf(a - (n + 1) * Ar0) <= 1e-4f * (n + 1) * fabsf(Ar0));
    }

    const float* wr = &dtw[(k * D_IN + d) * 6];
    float2 w0 = *(const float2*)wr;
    float2 w1 = *(const float2*)(wr + 2);
    float2 w2 = *(const float2*)(wr + 4);
    float bias = dtb[k * D_IN + d];

    int l0 = c * CLEN;
    int pos, dpos;
    dir_init(k, l0, pos, dpos);

    const float* uptr = &g_xc[b * L_LEN * D_IN + d];
    const float* pp   = &g_proj[(bk * L_LEN + l0) * 40];

    float S = 0.f;
    int ob = (bk * NCHUNK + c) * (D_IN * N_ST) + d * N_ST;

    if (pw) {
        u64 hp[8];
        #pragma unroll
        for (int j = 0; j < 8; j++) hp[j] = 0ull;
        for (int t = 0; t < CLEN; t++) {
            const float* base = pp + t * 40;
            float4 r0 = *(const float4*)base;
            float2 r1 = *(const float2*)(base + 4);
            ulonglong2 b01 = *(const ulonglong2*)(base + 8);   // {B0,B1},{B2,B3}
            ulonglong2 b23 = *(const ulonglong2*)(base + 12);  // {B4,B5},{B6,B7}
            ulonglong2 b45 = *(const ulonglong2*)(base + 16);  // {B8..B11}
            ulonglong2 b67 = *(const ulonglong2*)(base + 20);  // {B12..B15}
            float u = uptr[pos * D_IN];
            float dt = delta_of(r0, r1, w0, w1, w2, bias);
            S += dt;
            float dtu = dt * u;
            u64 dtu2 = pack2(dtu, dtu);
            u64 p[8];
            pow_tree_pk(__expf(dt * Ar0), p);
            hp[0] = fma2(p[0], hp[0], mul2(b01.x, dtu2));
            hp[1] = fma2(p[1], hp[1], mul2(b01.y, dtu2));
            hp[2] = fma2(p[2], hp[2], mul2(b23.x, dtu2));
            hp[3] = fma2(p[3], hp[3], mul2(b23.y, dtu2));
            hp[4] = fma2(p[4], hp[4], mul2(b45.x, dtu2));
            hp[5] = fma2(p[5], hp[5], mul2(b45.y, dtu2));
            hp[6] = fma2(p[6], hp[6], mul2(b67.x, dtu2));
            hp[7] = fma2(p[7], hp[7], mul2(b67.y, dtu2));
            pos = pos_step(pos, dpos);
        }
        #pragma unroll
        for (int j = 0; j < 8; j++) *(u64*)&g_cH[ob + 2 * j] = hp[j];
        float CA[N_ST];
        pow_tree16(__expf(Ar0 * S), CA);
        #pragma unroll
        for (int n = 0; n < N_ST; n += 4)
            *(float4*)&g_cA[ob + n] =
                make_float4(CA[n], CA[n+1], CA[n+2], CA[n+3]);
    } else {
        float arn[N_ST], h[N_ST];
        #pragma unroll
        for (int n = 0; n < N_ST; n++) { arn[n] = -__expf(al[n]); h[n] = 0.f; }
        for (int t = 0; t < CLEN; t++) {
            const float4* prow = (const float4*)(pp + t * 40);
            float4 r0 = prow[0];
            float2 r1 = *(const float2*)(pp + t * 40 + 4);
            float4 q0 = prow[2], q1 = prow[3], q2 = prow[4], q3 = prow[5];
            float u = uptr[pos * D_IN];
            float dt = delta_of(r0, r1, w0, w1, w2, bias);
            S += dt;
            float dtu = dt * u;
            float Bv[N_ST] = {q0.x,q0.y,q0.z,q0.w, q1.x,q1.y,q1.z,q1.w,
                              q2.x,q2.y,q2.z,q2.w, q3.x,q3.y,q3.z,q3.w};
            #pragma unroll
            for (int n = 0; n < N_ST; n++)
                h[n] = fmaf(__expf(dt * arn[n]), h[n], Bv[n] * dtu);
            pos = pos_step(pos, dpos);
        }
        #pragma unroll
        for (int n = 0; n < N_ST; n += 4) {
            *(float4*)&g_cH[ob+n] = make_float4(h[n],h[n+1],h[n+2],h[n+3]);
            *(float4*)&g_cA[ob+n] = make_float4(
                __expf(arn[n]*S),   __expf(arn[n+1]*S),
                __expf(arn[n+2]*S), __expf(arn[n+3]*S));
        }
    }
}

// Phase 2: scan over chunks per (b,k,d,n) channel; store entry state/chunk.
__global__ void __launch_bounds__(256) scan_phase2()
{
    int tid = blockIdx.x * 256 + threadIdx.x;      // < 16*3072
    int bk = tid / (D_IN * N_ST);
    int r  = tid % (D_IN * N_ST);
    float h = 0.f;
    #pragma unroll 4
    for (int c = 0; c < NCHUNK; c++) {
        int idx = (bk * NCHUNK + c) * (D_IN * N_ST) + r;
        g_hs[idx] = h;
        h = fmaf(g_cA[idx], h, g_cH[idx]);
    }
}

// ---------------------------------------------------------------------------
// Phase 3: re-run chunk with true entry state; dt inline; packed h + y.
// ---------------------------------------------------------------------------
__global__ void __launch_bounds__(192)
scan_phase3(const float* __restrict__ A_logs, const float* __restrict__ Ds,
            const float* __restrict__ dtw, const float* __restrict__ dtb)
{
    int bid = blockIdx.x;
    int c  = bid & (NCHUNK - 1);
    int bk = bid >> 6;
    int k = bk & 3, b = bk >> 2;
    int d = threadIdx.x;

    const float* al = &A_logs[(k * D_IN + d) * N_ST];
    float Ar0 = -__expf(al[0]);
    bool pw = true;
    #pragma unroll
    for (int n = 1; n < N_ST; n++) {
        float a = -__expf(al[n]);
        pw = pw && (fabsf(a - (n + 1) * Ar0) <= 1e-4f * (n + 1) * fabsf(Ar0));
    }

    const float* wr = &dtw[(k * D_IN + d) * 6];
    float2 w0 = *(const float2*)wr;
    float2 w1 = *(const float2*)(wr + 2);
    float2 w2 = *(const float2*)(wr + 4);
    float bias = dtb[k * D_IN + d];

    int hb = (bk * NCHUNK + c) * (D_IN * N_ST) + d * N_ST;

    int l0 = c * CLEN;
    int pos, dpos;
    dir_init(k, l0, pos, dpos);

    const float* uptr = &g_xc[b * L_LEN * D_IN + d];
    const float* pp   = &g_proj[(bk * L_LEN + l0) * 40];
    float* yptr = &g_yout[bk * L_LEN * D_IN + d];
    float Dv = Ds[k * D_IN + d];

    if (pw) {
        u64 hp[8];
        #pragma unroll
        for (int j = 0; j < 8; j++) hp[j] = *(const u64*)&g_hs[hb + 2 * j];
        for (int t = 0; t < CLEN; t++) {
            const float* base = pp + t * 40;
            float4 r0 = *(const float4*)base;
            float2 r1 = *(const float2*)(base + 4);
            ulonglong2 b01 = *(const ulonglong2*)(base + 8);
            ulonglong2 b23 = *(const ulonglong2*)(base + 12);
            ulonglong2 b45 = *(const ulonglong2*)(base + 16);
            ulonglong2 b67 = *(const ulonglong2*)(base + 20);
            ulonglong2 c01 = *(const ulonglong2*)(base + 24);
            ulonglong2 c23 = *(const ulonglong2*)(base + 28);
            ulonglong2 c45 = *(const ulonglong2*)(base + 32);
            ulonglong2 c67 = *(const ulonglong2*)(base + 36);
            float u = uptr[pos * D_IN];
            float dt = delta_of(r0, r1, w0, w1, w2, bias);
            float dtu = dt * u;
            u64 dtu2 = pack2(dtu, dtu);
            u64 p[8];
            pow_tree_pk(__expf(dt * Ar0), p);
            hp[0] = fma2(p[0], hp[0], mul2(b01.x, dtu2));
            hp[1] = fma2(p[1], hp[1], mul2(b01.y, dtu2));
            hp[2] = fma2(p[2], hp[2], mul2(b23.x, dtu2));
            hp[3] = fma2(p[3], hp[3], mul2(b23.y, dtu2));
            hp[4] = fma2(p[4], hp[4], mul2(b45.x, dtu2));
            hp[5] = fma2(p[5], hp[5], mul2(b45.y, dtu2));
            hp[6] = fma2(p[6], hp[6], mul2(b67.x, dtu2));
            hp[7] = fma2(p[7], hp[7], mul2(b67.y, dtu2));
            u64 ya = mul2(hp[0], c01.x);
            u64 yb = mul2(hp[1], c01.y);
            ya = fma2(hp[2], c23.x, ya);
            yb = fma2(hp[3], c23.y, yb);
            ya = fma2(hp[4], c45.x, ya);
            yb = fma2(hp[5], c45.y, yb);
            ya = fma2(hp[6], c67.x, ya);
            yb = fma2(hp[7], c67.y, yb);
            float2 va = unpk(ya), vb = unpk(yb);
            yptr[pos * D_IN] = va.x + va.y + vb.x + vb.y + Dv * u;
            pos = pos_step(pos, dpos);
        }
    } else {
        float arn[N_ST], h[N_ST];
        #pragma unroll
        for (int n = 0; n < N_ST; n++) arn[n] = -__expf(al[n]);
        #pragma unroll
        for (int n = 0; n < N_ST; n += 4) {
            float4 v = *(const float4*)&g_hs[hb + n];
            h[n] = v.x; h[n+1] = v.y; h[n+2] = v.z; h[n+3] = v.w;
        }
        for (int t = 0; t < CLEN; t++) {
            const float4* prow = (const float4*)(pp + t * 40);
            float4 r0v = prow[0];
            float2 r1v = *(const float2*)(pp + t * 40 + 4);
            float4 q0 = prow[2], q1 = prow[3], q2 = prow[4], q3 = prow[5];
            float4 c0 = prow[6], c1 = prow[7], c2 = prow[8], c3 = prow[9];
            float u = uptr[pos * D_IN];
            float dt = delta_of(r0v, r1v, w0, w1, w2, bias);
            float dtu = dt * u;
            float Bv[N_ST] = {q0.x,q0.y,q0.z,q0.w, q1.x,q1.y,q1.z,q1.w,
                              q2.x,q2.y,q2.z,q2.w, q3.x,q3.y,q3.z,q3.w};
            float Cv[N_ST] = {c0.x,c0.y,c0.z,c0.w, c1.x,c1.y,c1.z,c1.w,
                              c2.x,c2.y,c2.z,c2.w, c3.x,c3.y,c3.z,c3.w};
            float y0 = 0.f, y1 = 0.f;
            #pragma unroll
            for (int n = 0; n < N_ST; n += 2) {
                h[n]   = fmaf(__expf(dt * arn[n]),   h[n],   Bv[n]   * dtu);
                y0 = fmaf(h[n],   Cv[n],   y0);
                h[n+1] = fmaf(__expf(dt * arn[n+1]), h[n+1], Bv[n+1] * dtu);
                y1 = fmaf(h[n+1], Cv[n+1], y1);
            }
            yptr[pos * D_IN] = y0 + y1 + Dv * u;
            pos = pos_step(pos, dpos);
        }
    }
}

// ---------------------------------------------------------------------------
// Merge 4 directions + LayerNorm(192) + gate with z — one warp per position.
// ---------------------------------------------------------------------------
__global__ void __launch_bounds__(256)
merge_ln_kernel(const float* __restrict__ gamma, const float* __restrict__ beta)
{
    int warp = threadIdx.x >> 5, ln = threadIdx.x & 31;
    int m = blockIdx.x * 8 + warp;       // < 12544 (12544 = 1568*8)
    int b = m / L_LEN;
    int pos = m - b * L_LEN;

    float2 acc[3];
    #pragma unroll
    for (int seg = 0; seg < 3; seg++) {
        int dd = seg * 64 + ln * 2;
        float2 a = make_float2(0.f, 0.f);
        #pragma unroll
        for (int k = 0; k < 4; k++) {
            float2 v = *(const float2*)
                &g_yout[((b * 4 + k) * L_LEN + pos) * D_IN + dd];
            a.x += v.x; a.y += v.y;
        }
        acc[seg] = a;
    }

    float s = 0.f, s2 = 0.f;
    #pragma unroll
    for (int seg = 0; seg < 3; seg++) {
        s  += acc[seg].x + acc[seg].y;
        s2 += acc[seg].x * acc[seg].x + acc[seg].y * acc[seg].y;
    }
    #pragma unroll
    for (int o = 16; o > 0; o >>= 1) {
        s  += __shfl_xor_sync(0xffffffffu, s,  o);
        s2 += __shfl_xor_sync(0xffffffffu, s2, o);
    }
    float mu  = s * (1.f / 192.f);
    float var = s2 * (1.f / 192.f) - mu * mu;
    float rs  = rsqrtf(var + 1e-5f);

    #pragma unroll
    for (int seg = 0; seg < 3; seg++) {
        int dd = seg * 64 + ln * 2;
        float2 gm = *(const float2*)&gamma[dd];
        float2 bt = *(const float2*)&beta[dd];
        float2 zz = *(const float2*)&g_z[m * D_IN + dd];
        float2 o;
        o.x = fmaf((acc[seg].x - mu) * rs, gm.x, bt.x) * zz.x;
        o.y = fmaf((acc[seg].y - mu) * rs, gm.y, bt.y) * zz.y;
        *(float2*)&g_gated[m * D_IN + dd] = o;
    }
}

// ---------------------------------------------------------------------------
extern "C" void kernel_launch(void* const* d_in, const int* in_sizes, int n_in,
                              void* d_out, int out_size)
{
    const float* x      = (const float*)d_in[0];
    const float* in_w   = (const float*)d_in[1];
    const float* conv_w = (const float*)d_in[2];
    const float* conv_b = (const float*)d_in[3];
    const float* xpw    = (const float*)d_in[4];
    const float* dtw    = (const float*)d_in[5];
    const float* dtb    = (const float*)d_in[6];
    const float* A_logs = (const float*)d_in[7];
    const float* Ds     = (const float*)d_in[8];
    const float* gamma  = (const float*)d_in[9];
    const float* beta   = (const float*)d_in[10];
    const float* out_w  = (const float*)d_in[11];
    float* out = (float*)d_out;

    gemm_tn<0><<<dim3(M_ROWS / 64, 6, 1), 256>>>(x, in_w, nullptr, 384, 96);
    conv_dw_kernel<<<(M_ROWS * D_IN) / 256, 256>>>(conv_w, conv_b);
    gemm_tn<1><<<dim3(M_ROWS / 64, 3, 1), 256>>>(nullptr, xpw, nullptr, 152, 192);
    scan_phase1<<<16 * NCHUNK, 192>>>(A_logs, dtw, dtb);
    scan_phase2<<<(16 * D_IN * N_ST) / 256, 256>>>();
    scan_phase3<<<16 * NCHUNK, 192>>>(A_logs, Ds, dtw, dtb);
    merge_ln_kernel<<<M_ROWS / 8, 256>>>(gamma, beta);
    gemm_tn<2><<<dim3(M_ROWS / 64, 2, 1), 256>>>(nullptr, out_w, out, 96, 192);
}